// round 1
// baseline (speedup 1.0000x reference)
#include <cuda_runtime.h>
#include <cstdint>
#include <math.h>

// Shapes (fixed by the problem)
#define NN 2048      // tokens
#define CC 1024      // channels
#define HH 8         // heads
#define DD 128       // head dim

// Scratch (device globals -> no allocation in kernel_launch)
__device__ float g_v [(size_t)HH * NN * DD];        // v_cls      [h][n][e]   8 MB
__device__ float g_vn[(size_t)HH * NN * DD];        // normalized [h][n][e]   8 MB
__device__ float g_raw [(size_t)HH * NN * NN];      // v̂ v̂ᵀ      [h][n][m] 128 MB
__device__ float g_attn[(size_t)HH * NN * NN];      // softmax(raw*25)       128 MB

// ---------------------------------------------------------------------------
// Block reduce (256 threads, 8 warps)
// ---------------------------------------------------------------------------
__device__ __forceinline__ float block_reduce_max(float v, float* sh) {
    #pragma unroll
    for (int o = 16; o; o >>= 1) v = fmaxf(v, __shfl_xor_sync(0xffffffffu, v, o));
    int w = threadIdx.x >> 5, l = threadIdx.x & 31;
    if (l == 0) sh[w] = v;
    __syncthreads();
    float r = sh[0];
    #pragma unroll
    for (int i = 1; i < 8; i++) r = fmaxf(r, sh[i]);
    __syncthreads();
    return r;
}

__device__ __forceinline__ float block_reduce_sum(float v, float* sh) {
    #pragma unroll
    for (int o = 16; o; o >>= 1) v += __shfl_xor_sync(0xffffffffu, v, o);
    int w = threadIdx.x >> 5, l = threadIdx.x & 31;
    if (l == 0) sh[w] = v;
    __syncthreads();
    float r = sh[0];
    #pragma unroll
    for (int i = 1; i < 8; i++) r += sh[i];
    __syncthreads();
    return r;
}

// ---------------------------------------------------------------------------
// Kernel A: v = x @ Wv^T  (NT GEMM, M=2048, N=1024, K=1024)
//   writes g_v[h][n][e] and the x_ori half of the output: out[n][1024 + h*128+e]
// ---------------------------------------------------------------------------
__global__ __launch_bounds__(256, 2)
void kern_qkv(const float* __restrict__ X, const float* __restrict__ Wv,
              float* __restrict__ out) {
    const int m0 = blockIdx.y * 128;   // token tile
    const int n0 = blockIdx.x * 128;   // output-channel tile (0..1023)
    __shared__ float As[32][132];
    __shared__ float Bs[32][132];
    const int tid = threadIdx.x;
    const int tx = tid & 15, ty = tid >> 4;
    float acc[8][8] = {};

    const int r = tid >> 3, cq = tid & 7;
    for (int k0 = 0; k0 < CC; k0 += 32) {
        #pragma unroll
        for (int p = 0; p < 4; ++p) {
            const int mm = r + p * 32;
            float4 a = *(const float4*)&X [(size_t)(m0 + mm) * CC + k0 + cq * 4];
            As[cq*4+0][mm] = a.x; As[cq*4+1][mm] = a.y;
            As[cq*4+2][mm] = a.z; As[cq*4+3][mm] = a.w;
            float4 b = *(const float4*)&Wv[(size_t)(n0 + mm) * CC + k0 + cq * 4];
            Bs[cq*4+0][mm] = b.x; Bs[cq*4+1][mm] = b.y;
            Bs[cq*4+2][mm] = b.z; Bs[cq*4+3][mm] = b.w;
        }
        __syncthreads();
        #pragma unroll 8
        for (int k = 0; k < 32; ++k) {
            float4 a0 = *(const float4*)&As[k][ty * 8];
            float4 a1 = *(const float4*)&As[k][ty * 8 + 4];
            float4 b0 = *(const float4*)&Bs[k][tx * 8];
            float4 b1 = *(const float4*)&Bs[k][tx * 8 + 4];
            float a[8] = {a0.x,a0.y,a0.z,a0.w,a1.x,a1.y,a1.z,a1.w};
            float b[8] = {b0.x,b0.y,b0.z,b0.w,b1.x,b1.y,b1.z,b1.w};
            #pragma unroll
            for (int i = 0; i < 8; i++)
                #pragma unroll
                for (int j = 0; j < 8; j++)
                    acc[i][j] = fmaf(a[i], b[j], acc[i][j]);
        }
        __syncthreads();
    }

    #pragma unroll
    for (int i = 0; i < 8; i++) {
        const int n = m0 + ty * 8 + i;
        #pragma unroll
        for (int j = 0; j < 8; j++) {
            const int col = n0 + tx * 8 + j;       // 0..1023
            const int h = col >> 7, e = col & 127;
            const float v = acc[i][j];
            g_v[((size_t)h * NN + n) * DD + e] = v;
            out[(size_t)n * (2 * CC) + CC + col] = v;   // x_ori half
        }
    }
}

// ---------------------------------------------------------------------------
// Kernel B: per-(h,n) L2 normalize (one warp per row)
// ---------------------------------------------------------------------------
__global__ __launch_bounds__(256)
void kern_norm() {
    const int idx = blockIdx.x * blockDim.x + threadIdx.x;
    const int row = idx >> 5;         // 0..16383
    const int lane = idx & 31;
    const float4 x = *(const float4*)(g_v + (size_t)row * DD + lane * 4);
    float s = x.x*x.x + x.y*x.y + x.z*x.z + x.w*x.w;
    #pragma unroll
    for (int o = 16; o; o >>= 1) s += __shfl_xor_sync(0xffffffffu, s, o);
    const float inv = rsqrtf(s);
    float4 y = {x.x*inv, x.y*inv, x.z*inv, x.w*inv};
    *(float4*)(g_vn + (size_t)row * DD + lane * 4) = y;
}

// ---------------------------------------------------------------------------
// Kernel C: raw[h] = v̂[h] @ v̂[h]^T  (NT GEMM per head, M=N=2048, K=128)
// ---------------------------------------------------------------------------
__global__ __launch_bounds__(256, 2)
void kern_score() {
    const int h = blockIdx.z;
    const float* __restrict__ A = g_vn + (size_t)h * NN * DD;
    float* __restrict__ C = g_raw + (size_t)h * NN * NN;
    const int m0 = blockIdx.y * 128, n0 = blockIdx.x * 128;
    __shared__ float As[32][132];
    __shared__ float Bs[32][132];
    const int tid = threadIdx.x;
    const int tx = tid & 15, ty = tid >> 4;
    float acc[8][8] = {};

    const int r = tid >> 3, cq = tid & 7;
    for (int k0 = 0; k0 < DD; k0 += 32) {
        #pragma unroll
        for (int p = 0; p < 4; ++p) {
            const int mm = r + p * 32;
            float4 a = *(const float4*)&A[(size_t)(m0 + mm) * DD + k0 + cq * 4];
            As[cq*4+0][mm] = a.x; As[cq*4+1][mm] = a.y;
            As[cq*4+2][mm] = a.z; As[cq*4+3][mm] = a.w;
            float4 b = *(const float4*)&A[(size_t)(n0 + mm) * DD + k0 + cq * 4];
            Bs[cq*4+0][mm] = b.x; Bs[cq*4+1][mm] = b.y;
            Bs[cq*4+2][mm] = b.z; Bs[cq*4+3][mm] = b.w;
        }
        __syncthreads();
        #pragma unroll 8
        for (int k = 0; k < 32; ++k) {
            float4 a0 = *(const float4*)&As[k][ty * 8];
            float4 a1 = *(const float4*)&As[k][ty * 8 + 4];
            float4 b0 = *(const float4*)&Bs[k][tx * 8];
            float4 b1 = *(const float4*)&Bs[k][tx * 8 + 4];
            float a[8] = {a0.x,a0.y,a0.z,a0.w,a1.x,a1.y,a1.z,a1.w};
            float b[8] = {b0.x,b0.y,b0.z,b0.w,b1.x,b1.y,b1.z,b1.w};
            #pragma unroll
            for (int i = 0; i < 8; i++)
                #pragma unroll
                for (int j = 0; j < 8; j++)
                    acc[i][j] = fmaf(a[i], b[j], acc[i][j]);
        }
        __syncthreads();
    }

    #pragma unroll
    for (int i = 0; i < 8; i++) {
        const size_t rowoff = (size_t)(m0 + ty * 8 + i) * NN + n0 + tx * 8;
        float4 c0 = {acc[i][0], acc[i][1], acc[i][2], acc[i][3]};
        float4 c1 = {acc[i][4], acc[i][5], acc[i][6], acc[i][7]};
        *(float4*)&C[rowoff]     = c0;
        *(float4*)&C[rowoff + 4] = c1;
    }
}

// ---------------------------------------------------------------------------
// Kernel D: attn = softmax(raw * 25, axis=-1), one block per (h,n) row
// ---------------------------------------------------------------------------
__global__ __launch_bounds__(256)
void kern_softmax() {
    __shared__ float sh[8];
    const size_t off = ((size_t)blockIdx.y * NN + blockIdx.x) * NN;
    const int t = threadIdx.x;
    float4 v0 = *(const float4*)(g_raw + off + t * 8);
    float4 v1 = *(const float4*)(g_raw + off + t * 8 + 4);
    float v[8] = {v0.x,v0.y,v0.z,v0.w,v1.x,v1.y,v1.z,v1.w};
    float mx = -1e30f;
    #pragma unroll
    for (int i = 0; i < 8; i++) { v[i] *= 25.0f; mx = fmaxf(mx, v[i]); }
    mx = block_reduce_max(mx, sh);
    float s = 0.0f;
    #pragma unroll
    for (int i = 0; i < 8; i++) { v[i] = __expf(v[i] - mx); s += v[i]; }
    s = block_reduce_sum(s, sh);
    const float inv = 1.0f / s;
    float4 o0 = {v[0]*inv, v[1]*inv, v[2]*inv, v[3]*inv};
    float4 o1 = {v[4]*inv, v[5]*inv, v[6]*inv, v[7]*inv};
    *(float4*)(g_attn + off + t * 8)     = o0;
    *(float4*)(g_attn + off + t * 8 + 4) = o1;
}

// ---------------------------------------------------------------------------
// Kernel E: x[h] = attn[h] @ v[h]  (NN GEMM, M=2048, N=128, K=2048)
//   writes the x half of the output: out[n][h*128+e]
// ---------------------------------------------------------------------------
__global__ __launch_bounds__(256, 2)
void kern_out(float* __restrict__ out) {
    const int h = blockIdx.z;
    const float* __restrict__ A = g_attn + (size_t)h * NN * NN;   // [n][m]
    const float* __restrict__ B = g_v    + (size_t)h * NN * DD;   // [m][e]
    const int m0 = blockIdx.y * 128;
    __shared__ float As[32][132];
    __shared__ float Bs[32][132];
    const int tid = threadIdx.x;
    const int tx = tid & 15, ty = tid >> 4;
    float acc[8][8] = {};

    const int r = tid >> 3, cq = tid & 7;
    const int kk = tid >> 5, c4 = tid & 31;
    for (int k0 = 0; k0 < NN; k0 += 32) {
        #pragma unroll
        for (int p = 0; p < 4; ++p) {
            const int mm = r + p * 32;
            float4 a = *(const float4*)&A[(size_t)(m0 + mm) * NN + k0 + cq * 4];
            As[cq*4+0][mm] = a.x; As[cq*4+1][mm] = a.y;
            As[cq*4+2][mm] = a.z; As[cq*4+3][mm] = a.w;
        }
        #pragma unroll
        for (int p = 0; p < 4; ++p) {
            const int k = kk + p * 8;
            *(float4*)&Bs[k][c4 * 4] =
                *(const float4*)&B[(size_t)(k0 + k) * DD + c4 * 4];
        }
        __syncthreads();
        #pragma unroll 8
        for (int k = 0; k < 32; ++k) {
            float4 a0 = *(const float4*)&As[k][ty * 8];
            float4 a1 = *(const float4*)&As[k][ty * 8 + 4];
            float4 b0 = *(const float4*)&Bs[k][tx * 8];
            float4 b1 = *(const float4*)&Bs[k][tx * 8 + 4];
            float a[8] = {a0.x,a0.y,a0.z,a0.w,a1.x,a1.y,a1.z,a1.w};
            float b[8] = {b0.x,b0.y,b0.z,b0.w,b1.x,b1.y,b1.z,b1.w};
            #pragma unroll
            for (int i = 0; i < 8; i++)
                #pragma unroll
                for (int j = 0; j < 8; j++)
                    acc[i][j] = fmaf(a[i], b[j], acc[i][j]);
        }
        __syncthreads();
    }

    #pragma unroll
    for (int i = 0; i < 8; i++) {
        const int n = m0 + ty * 8 + i;
        const size_t rowoff = (size_t)n * (2 * CC) + h * DD + tx * 8;
        float4 c0 = {acc[i][0], acc[i][1], acc[i][2], acc[i][3]};
        float4 c1 = {acc[i][4], acc[i][5], acc[i][6], acc[i][7]};
        *(float4*)&out[rowoff]     = c0;
        *(float4*)&out[rowoff + 4] = c1;
    }
}

// ---------------------------------------------------------------------------
// Kernel F: sim_round2. One block per row n.
//   acr_sum = Σ_h raw ; keep = acr_sum > 6.0 (== mean > 0.75)
//   sa = Σ_h attn / 8 ; out = keep * exp(sa - max) / Σ(keep * exp(sa - max))
//   (softmax denominator cancels in the masked renormalization)
// ---------------------------------------------------------------------------
__global__ __launch_bounds__(256)
void kern_sim(float* __restrict__ out) {
    __shared__ float sh[8];
    const int n = blockIdx.x;
    const int t = threadIdx.x;
    float sa[8] = {}, ar[8] = {};
    #pragma unroll
    for (int h = 0; h < HH; ++h) {
        const size_t off = ((size_t)h * NN + n) * NN + t * 8;
        float4 r0 = *(const float4*)(g_raw + off);
        float4 r1 = *(const float4*)(g_raw + off + 4);
        float4 a0 = *(const float4*)(g_attn + off);
        float4 a1 = *(const float4*)(g_attn + off + 4);
        ar[0]+=r0.x; ar[1]+=r0.y; ar[2]+=r0.z; ar[3]+=r0.w;
        ar[4]+=r1.x; ar[5]+=r1.y; ar[6]+=r1.z; ar[7]+=r1.w;
        sa[0]+=a0.x; sa[1]+=a0.y; sa[2]+=a0.z; sa[3]+=a0.w;
        sa[4]+=a1.x; sa[5]+=a1.y; sa[6]+=a1.z; sa[7]+=a1.w;
    }
    float mx = -1e30f;
    #pragma unroll
    for (int i = 0; i < 8; i++) { sa[i] *= 0.125f; mx = fmaxf(mx, sa[i]); }
    mx = block_reduce_max(mx, sh);
    float e[8]; float ms = 0.0f;
    #pragma unroll
    for (int i = 0; i < 8; i++) {
        float ev = __expf(sa[i] - mx);
        ev = (ar[i] > 6.0f) ? ev : 0.0f;
        e[i] = ev; ms += ev;
    }
    ms = block_reduce_sum(ms, sh);
    const float inv = 1.0f / ms;
    const size_t base = (size_t)NN * (2 * CC) + (size_t)n * NN + t * 8;
    float4 o0 = {e[0]*inv, e[1]*inv, e[2]*inv, e[3]*inv};
    float4 o1 = {e[4]*inv, e[5]*inv, e[6]*inv, e[7]*inv};
    *(float4*)(out + base)     = o0;
    *(float4*)(out + base + 4) = o1;
}

// ---------------------------------------------------------------------------
extern "C" void kernel_launch(void* const* d_in, const int* in_sizes, int n_in,
                              void* d_out, int out_size) {
    const float* x_cls = (const float*)d_in[0];
    const float* W_cls = (const float*)d_in[4];
    float* out = (float*)d_out;

    const float* Wv = W_cls + (size_t)2 * CC * CC;   // v rows of the qkv weight

    kern_qkv    <<<dim3(CC/128, NN/128), 256>>>(x_cls, Wv, out);
    kern_norm   <<<(HH*NN*32)/256, 256>>>();
    kern_score  <<<dim3(NN/128, NN/128, HH), 256>>>();
    kern_softmax<<<dim3(NN, HH), 256>>>();
    kern_out    <<<dim3(1, NN/128, HH), 256>>>(out);
    kern_sim    <<<NN, 256>>>(out);
}

// round 2
// speedup vs baseline: 2.5863x; 2.5863x over previous
#include <cuda_runtime.h>
#include <cuda_bf16.h>
#include <cstdint>
#include <math.h>

#define NN 2048
#define CC 1024
#define HH 8
#define DD 128

using bf16 = __nv_bfloat16;

// Scratch (device globals — no allocations anywhere)
__device__ float g_v   [(size_t)HH * NN * DD];   // fp32 v           8 MB
__device__ bf16  g_vhat[(size_t)HH * NN * DD];   // normalized bf16  4 MB
__device__ bf16  g_vb  [(size_t)HH * NN * DD];   // v bf16           4 MB
__device__ bf16  g_raw [(size_t)HH * NN * NN];   // v̂v̂ᵀ bf16        64 MB
__device__ float g_m25 [HH * NN];                // 25*rowmax
__device__ float g_invZ[HH * NN];                // 1/rowsum

// ---------------------------------------------------------------------------
// helpers
// ---------------------------------------------------------------------------
__device__ __forceinline__ uint32_t sptr(const void* p) {
    return (uint32_t)__cvta_generic_to_shared(p);
}
__device__ __forceinline__ void ldmx4(uint32_t a, uint32_t& r0, uint32_t& r1,
                                      uint32_t& r2, uint32_t& r3) {
    asm volatile("ldmatrix.sync.aligned.m8n8.x4.shared.b16 {%0,%1,%2,%3}, [%4];"
                 : "=r"(r0), "=r"(r1), "=r"(r2), "=r"(r3) : "r"(a));
}
__device__ __forceinline__ void ldmx4t(uint32_t a, uint32_t& r0, uint32_t& r1,
                                       uint32_t& r2, uint32_t& r3) {
    asm volatile("ldmatrix.sync.aligned.m8n8.x4.trans.shared.b16 {%0,%1,%2,%3}, [%4];"
                 : "=r"(r0), "=r"(r1), "=r"(r2), "=r"(r3) : "r"(a));
}
__device__ __forceinline__ void mma_bf(float* c, const uint32_t* a,
                                       uint32_t b0, uint32_t b1) {
    asm volatile("mma.sync.aligned.m16n8k16.row.col.f32.bf16.bf16.f32 "
                 "{%0,%1,%2,%3}, {%4,%5,%6,%7}, {%8,%9}, {%0,%1,%2,%3};"
                 : "+f"(c[0]), "+f"(c[1]), "+f"(c[2]), "+f"(c[3])
                 : "r"(a[0]), "r"(a[1]), "r"(a[2]), "r"(a[3]), "r"(b0), "r"(b1));
}
__device__ __forceinline__ uint32_t packbf(float x, float y) {
    __nv_bfloat162 h = __floats2bfloat162_rn(x, y);
    return *reinterpret_cast<uint32_t*>(&h);
}
__device__ __forceinline__ void split2(float x, float y, uint32_t& hi, uint32_t& lo) {
    bf16 hx = __float2bfloat16_rn(x), hy = __float2bfloat16_rn(y);
    bf16 lx = __float2bfloat16_rn(x - __bfloat162float(hx));
    bf16 ly = __float2bfloat16_rn(y - __bfloat162float(hy));
    __nv_bfloat162 H = __halves2bfloat162(hx, hy);
    __nv_bfloat162 L = __halves2bfloat162(lx, ly);
    hi = *reinterpret_cast<uint32_t*>(&H);
    lo = *reinterpret_cast<uint32_t*>(&L);
}

__device__ __forceinline__ float block_reduce_max(float v, float* sh) {
    #pragma unroll
    for (int o = 16; o; o >>= 1) v = fmaxf(v, __shfl_xor_sync(0xffffffffu, v, o));
    int w = threadIdx.x >> 5, l = threadIdx.x & 31;
    if (l == 0) sh[w] = v;
    __syncthreads();
    float r = sh[0];
    #pragma unroll
    for (int i = 1; i < 8; i++) r = fmaxf(r, sh[i]);
    __syncthreads();
    return r;
}
__device__ __forceinline__ float block_reduce_sum(float v, float* sh) {
    #pragma unroll
    for (int o = 16; o; o >>= 1) v += __shfl_xor_sync(0xffffffffu, v, o);
    int w = threadIdx.x >> 5, l = threadIdx.x & 31;
    if (l == 0) sh[w] = v;
    __syncthreads();
    float r = sh[0];
    #pragma unroll
    for (int i = 1; i < 8; i++) r += sh[i];
    __syncthreads();
    return r;
}

// ---------------------------------------------------------------------------
// Kernel 1: v = X @ Wv^T via split-bf16 (hi+lo) tensor-core GEMM.
// NT GEMM: A = X [2048,1024] rowmajor, B = Wv [1024,1024] rowmajor ([N,K]).
// Block 128x128, BK=32. Writes g_v fp32 and the x_ori output half.
// ---------------------------------------------------------------------------
__global__ __launch_bounds__(256)
void kern_qkv(const float* __restrict__ X, const float* __restrict__ Wv,
              float* __restrict__ out) {
    __shared__ __align__(16) bf16 Ah[128][40], Al[128][40], Bh[128][40], Bl[128][40];
    uint32_t* AhU = (uint32_t*)&Ah[0][0]; uint32_t* AlU = (uint32_t*)&Al[0][0];
    uint32_t* BhU = (uint32_t*)&Bh[0][0]; uint32_t* BlU = (uint32_t*)&Bl[0][0];

    const int m0 = blockIdx.y * 128, n0 = blockIdx.x * 128;
    const int tid = threadIdx.x, lane = tid & 31, wid = tid >> 5;
    const int wm = wid & 3, wn = wid >> 2;
    const int fr = lane & 15, fc = (lane >> 4) * 8;
    const int lr = tid >> 1, lh = tid & 1;

    float acc[2][8][4] = {};

    for (int k0 = 0; k0 < CC; k0 += 32) {
        #pragma unroll
        for (int i = 0; i < 4; i++) {
            const int c = lh * 16 + i * 4;
            float4 a = *(const float4*)&X [(size_t)(m0 + lr) * CC + k0 + c];
            float4 b = *(const float4*)&Wv[(size_t)(n0 + lr) * CC + k0 + c];
            uint32_t h0, l0, h1, l1;
            split2(a.x, a.y, h0, l0); split2(a.z, a.w, h1, l1);
            AhU[lr * 20 + c / 2] = h0; AhU[lr * 20 + c / 2 + 1] = h1;
            AlU[lr * 20 + c / 2] = l0; AlU[lr * 20 + c / 2 + 1] = l1;
            split2(b.x, b.y, h0, l0); split2(b.z, b.w, h1, l1);
            BhU[lr * 20 + c / 2] = h0; BhU[lr * 20 + c / 2 + 1] = h1;
            BlU[lr * 20 + c / 2] = l0; BlU[lr * 20 + c / 2 + 1] = l1;
        }
        __syncthreads();
        #pragma unroll
        for (int ks = 0; ks < 32; ks += 16) {
            uint32_t ah[2][4], al[2][4], bh[4][4], bl[4][4];
            #pragma unroll
            for (int i = 0; i < 2; i++) {
                ldmx4(sptr(&Ah[wm * 32 + i * 16 + fr][ks + fc]),
                      ah[i][0], ah[i][1], ah[i][2], ah[i][3]);
                ldmx4(sptr(&Al[wm * 32 + i * 16 + fr][ks + fc]),
                      al[i][0], al[i][1], al[i][2], al[i][3]);
            }
            #pragma unroll
            for (int j = 0; j < 4; j++) {
                ldmx4(sptr(&Bh[wn * 64 + j * 16 + fr][ks + fc]),
                      bh[j][0], bh[j][1], bh[j][2], bh[j][3]);
                ldmx4(sptr(&Bl[wn * 64 + j * 16 + fr][ks + fc]),
                      bl[j][0], bl[j][1], bl[j][2], bl[j][3]);
            }
            #pragma unroll
            for (int i = 0; i < 2; i++)
                #pragma unroll
                for (int j = 0; j < 4; j++) {
                    // non-trans pairing: ntile 2j uses {r0,r2}; 2j+1 uses {r1,r3}
                    mma_bf(acc[i][2*j],   ah[i], bh[j][0], bh[j][2]);
                    mma_bf(acc[i][2*j+1], ah[i], bh[j][1], bh[j][3]);
                    mma_bf(acc[i][2*j],   ah[i], bl[j][0], bl[j][2]);
                    mma_bf(acc[i][2*j+1], ah[i], bl[j][1], bl[j][3]);
                    mma_bf(acc[i][2*j],   al[i], bh[j][0], bh[j][2]);
                    mma_bf(acc[i][2*j+1], al[i], bh[j][1], bh[j][3]);
                }
        }
        __syncthreads();
    }

    const int g = lane >> 2, t2 = (lane & 3) * 2;
    const int h = n0 >> 7;
    #pragma unroll
    for (int i = 0; i < 2; i++)
        #pragma unroll
        for (int half = 0; half < 2; half++) {
            const int row = m0 + wm * 32 + i * 16 + g + half * 8;
            #pragma unroll
            for (int j = 0; j < 8; j++) {
                const int e = wn * 64 + j * 8 + t2;  // within-head dim (n0 is 128-aligned)
                float2 v = make_float2(acc[i][j][half*2], acc[i][j][half*2+1]);
                *(float2*)&g_v[((size_t)h * NN + row) * DD + e] = v;
                *(float2*)&out[(size_t)row * (2*CC) + CC + n0 + e] = v;
            }
        }
}

// ---------------------------------------------------------------------------
// Kernel 2: per-row L2 normalize; emit v̂ (bf16) and v (bf16)
// ---------------------------------------------------------------------------
__global__ __launch_bounds__(256)
void kern_norm() {
    const int idx = blockIdx.x * blockDim.x + threadIdx.x;
    const int row = idx >> 5, lane = idx & 31;
    const float4 x = *(const float4*)&g_v[(size_t)row * DD + lane * 4];
    float s = x.x*x.x + x.y*x.y + x.z*x.z + x.w*x.w;
    #pragma unroll
    for (int o = 16; o; o >>= 1) s += __shfl_xor_sync(0xffffffffu, s, o);
    const float inv = rsqrtf(s);
    *(uint2*)&g_vb  [(size_t)row * DD + lane * 4] =
        make_uint2(packbf(x.x, x.y), packbf(x.z, x.w));
    *(uint2*)&g_vhat[(size_t)row * DD + lane * 4] =
        make_uint2(packbf(x.x*inv, x.y*inv), packbf(x.z*inv, x.w*inv));
}

// ---------------------------------------------------------------------------
// Kernel 3: raw[h] = v̂ v̂ᵀ (bf16 NT tensor-core GEMM, K=128), store bf16
// ---------------------------------------------------------------------------
__global__ __launch_bounds__(256)
void kern_score() {
    __shared__ __align__(16) bf16 As[128][72], Bs[128][72];
    const int h = blockIdx.z;
    const bf16* __restrict__ V = g_vhat + (size_t)h * NN * DD;
    bf16* __restrict__ C = g_raw + (size_t)h * NN * NN;
    const int m0 = blockIdx.y * 128, n0 = blockIdx.x * 128;
    const int tid = threadIdx.x, lane = tid & 31, wid = tid >> 5;
    const int wm = wid & 3, wn = wid >> 2;
    const int fr = lane & 15, fc = (lane >> 4) * 8;
    const int lr = tid >> 1, lh = tid & 1;

    float acc[2][8][4] = {};

    for (int k0 = 0; k0 < DD; k0 += 64) {
        #pragma unroll
        for (int i = 0; i < 4; i++) {
            const int c = lh * 32 + i * 8;
            *(uint4*)&As[lr][c] = *(const uint4*)&V[(size_t)(m0 + lr) * DD + k0 + c];
            *(uint4*)&Bs[lr][c] = *(const uint4*)&V[(size_t)(n0 + lr) * DD + k0 + c];
        }
        __syncthreads();
        #pragma unroll
        for (int ks = 0; ks < 64; ks += 16) {
            uint32_t a_[2][4], b_[4][4];
            #pragma unroll
            for (int i = 0; i < 2; i++)
                ldmx4(sptr(&As[wm * 32 + i * 16 + fr][ks + fc]),
                      a_[i][0], a_[i][1], a_[i][2], a_[i][3]);
            #pragma unroll
            for (int j = 0; j < 4; j++)
                ldmx4(sptr(&Bs[wn * 64 + j * 16 + fr][ks + fc]),
                      b_[j][0], b_[j][1], b_[j][2], b_[j][3]);
            #pragma unroll
            for (int i = 0; i < 2; i++)
                #pragma unroll
                for (int j = 0; j < 4; j++) {
                    mma_bf(acc[i][2*j],   a_[i], b_[j][0], b_[j][2]);
                    mma_bf(acc[i][2*j+1], a_[i], b_[j][1], b_[j][3]);
                }
        }
        __syncthreads();
    }

    const int g = lane >> 2, t2 = (lane & 3) * 2;
    #pragma unroll
    for (int i = 0; i < 2; i++)
        #pragma unroll
        for (int half = 0; half < 2; half++) {
            const int row = m0 + wm * 32 + i * 16 + g + half * 8;
            #pragma unroll
            for (int j = 0; j < 8; j++) {
                const int col = n0 + wn * 64 + j * 8 + t2;
                *(uint32_t*)&C[(size_t)row * NN + col] =
                    packbf(acc[i][j][half*2], acc[i][j][half*2+1]);
            }
        }
}

// ---------------------------------------------------------------------------
// Kernel 4: per-row softmax stats of 25*raw: m25 = 25*max, invZ = 1/sum exp
// ---------------------------------------------------------------------------
__global__ __launch_bounds__(256)
void kern_stats() {
    __shared__ float sh[8];
    const size_t off = (size_t)blockIdx.x * NN;
    const int t = threadIdx.x;
    uint4 u = *(const uint4*)&g_raw[off + t * 8];
    const bf16* p = (const bf16*)&u;
    float v[8];
    float mx = -2.0f;
    #pragma unroll
    for (int i = 0; i < 8; i++) { v[i] = __bfloat162float(p[i]); mx = fmaxf(mx, v[i]); }
    mx = block_reduce_max(mx, sh);
    const float m25 = 25.0f * mx;
    float s = 0.0f;
    #pragma unroll
    for (int i = 0; i < 8; i++) s += __expf(25.0f * v[i] - m25);
    s = block_reduce_sum(s, sh);
    if (t == 0) { g_m25[blockIdx.x] = m25; g_invZ[blockIdx.x] = 1.0f / s; }
}

// ---------------------------------------------------------------------------
// Kernel 5: x[h] = P_offdiag @ v (bf16 MMA, p computed on the fly from raw)
//           + exact fp32 diagonal term p_nn * v_n in the epilogue.
// ---------------------------------------------------------------------------
__global__ __launch_bounds__(256)
void kern_out(float* __restrict__ out) {
    __shared__ __align__(16) bf16 Ap[128][40];
    __shared__ __align__(16) bf16 Vs[32][136];
    const int h = blockIdx.y, m0 = blockIdx.x * 128;
    const bf16* __restrict__ R  = g_raw + (size_t)h * NN * NN;
    const bf16* __restrict__ Vb = g_vb  + (size_t)h * NN * DD;
    const int tid = threadIdx.x, lane = tid & 31, wid = tid >> 5;
    const int wm = wid & 3, wn = wid >> 2;
    const int fr = lane & 15, fc = (lane >> 4) * 8;
    const int lr = tid >> 1, lh = tid & 1;
    const int vk = tid >> 3, vc = (tid & 7) * 16;

    const float m25 = g_m25[h * NN + m0 + lr];
    const float iz  = g_invZ[h * NN + m0 + lr];

    float acc[2][8][4] = {};

    for (int k0 = 0; k0 < NN; k0 += 32) {
        #pragma unroll
        for (int i = 0; i < 2; i++) {
            const int c = lh * 16 + i * 8;
            uint4 u = *(const uint4*)&R[(size_t)(m0 + lr) * NN + k0 + c];
            const bf16* pb = (const bf16*)&u;
            uint32_t o[4];
            #pragma unroll
            for (int e = 0; e < 4; e++) {
                float p0 = __expf(25.0f * __bfloat162float(pb[2*e])   - m25) * iz;
                float p1 = __expf(25.0f * __bfloat162float(pb[2*e+1]) - m25) * iz;
                if (k0 + c + 2*e     == m0 + lr) p0 = 0.0f;   // diagonal handled in epilogue
                if (k0 + c + 2*e + 1 == m0 + lr) p1 = 0.0f;
                o[e] = packbf(p0, p1);
            }
            uint4 w; w.x = o[0]; w.y = o[1]; w.z = o[2]; w.w = o[3];
            *(uint4*)&Ap[lr][c] = w;
        }
        #pragma unroll
        for (int i = 0; i < 2; i++)
            *(uint4*)&Vs[vk][vc + i * 8] =
                *(const uint4*)&Vb[(size_t)(k0 + vk) * DD + vc + i * 8];
        __syncthreads();
        #pragma unroll
        for (int ks = 0; ks < 32; ks += 16) {
            uint32_t a_[2][4], b_[4][4];
            #pragma unroll
            for (int i = 0; i < 2; i++)
                ldmx4(sptr(&Ap[wm * 32 + i * 16 + fr][ks + fc]),
                      a_[i][0], a_[i][1], a_[i][2], a_[i][3]);
            #pragma unroll
            for (int j = 0; j < 4; j++)
                ldmx4t(sptr(&Vs[ks + fr][wn * 64 + j * 16 + fc]),
                       b_[j][0], b_[j][1], b_[j][2], b_[j][3]);
            #pragma unroll
            for (int i = 0; i < 2; i++)
                #pragma unroll
                for (int j = 0; j < 4; j++) {
                    // trans pairing: ntile 2j = {r0,r1}; 2j+1 = {r2,r3}
                    mma_bf(acc[i][2*j],   a_[i], b_[j][0], b_[j][1]);
                    mma_bf(acc[i][2*j+1], a_[i], b_[j][2], b_[j][3]);
                }
        }
        __syncthreads();
    }

    const int g = lane >> 2, t2 = (lane & 3) * 2;
    #pragma unroll
    for (int i = 0; i < 2; i++)
        #pragma unroll
        for (int half = 0; half < 2; half++) {
            const int row = m0 + wm * 32 + i * 16 + g + half * 8;
            const float rawnn = __bfloat162float(R[(size_t)row * NN + row]);
            const float pd = __expf(25.0f * rawnn - g_m25[h * NN + row]) * g_invZ[h * NN + row];
            #pragma unroll
            for (int j = 0; j < 8; j++) {
                const int e = wn * 64 + j * 8 + t2;
                float2 vv = *(const float2*)&g_v[((size_t)h * NN + row) * DD + e];
                float2 o = make_float2(acc[i][j][half*2]   + pd * vv.x,
                                       acc[i][j][half*2+1] + pd * vv.y);
                *(float2*)&out[(size_t)row * (2*CC) + h * DD + e] = o;
            }
        }
}

// ---------------------------------------------------------------------------
// Kernel 6: sim_round2. attn regenerated from raw + stats; masked renorm.
// ---------------------------------------------------------------------------
__global__ __launch_bounds__(256)
void kern_sim(float* __restrict__ out) {
    __shared__ float sh[8];
    const int n = blockIdx.x, t = threadIdx.x;
    float sa[8] = {}, ar[8] = {};
    #pragma unroll
    for (int h = 0; h < HH; h++) {
        const size_t off = ((size_t)h * NN + n) * NN + t * 8;
        uint4 u = *(const uint4*)&g_raw[off];
        const bf16* pb = (const bf16*)&u;
        const float m25 = g_m25[h * NN + n], iz = g_invZ[h * NN + n];
        #pragma unroll
        for (int i = 0; i < 8; i++) {
            const float v = __bfloat162float(pb[i]);
            ar[i] += v;
            sa[i] += __expf(25.0f * v - m25) * iz;
        }
    }
    float mx = -1e30f;
    #pragma unroll
    for (int i = 0; i < 8; i++) { sa[i] *= 0.125f; mx = fmaxf(mx, sa[i]); }
    mx = block_reduce_max(mx, sh);
    float e[8]; float ms = 0.0f;
    #pragma unroll
    for (int i = 0; i < 8; i++) {
        float ev = __expf(sa[i] - mx);
        ev = (ar[i] > 6.0f) ? ev : 0.0f;   // mean>0.75  <=>  sum>6
        e[i] = ev; ms += ev;
    }
    ms = block_reduce_sum(ms, sh);
    const float inv = 1.0f / ms;
    const size_t base = (size_t)NN * (2*CC) + (size_t)n * NN + t * 8;
    *(float4*)&out[base]     = make_float4(e[0]*inv, e[1]*inv, e[2]*inv, e[3]*inv);
    *(float4*)&out[base + 4] = make_float4(e[4]*inv, e[5]*inv, e[6]*inv, e[7]*inv);
}

// ---------------------------------------------------------------------------
extern "C" void kernel_launch(void* const* d_in, const int* in_sizes, int n_in,
                              void* d_out, int out_size) {
    const float* x_cls = (const float*)d_in[0];
    const float* W_cls = (const float*)d_in[4];
    float* out = (float*)d_out;
    const float* Wv = W_cls + (size_t)2 * CC * CC;

    kern_qkv  <<<dim3(8, 16), 256>>>(x_cls, Wv, out);
    kern_norm <<<(HH * NN * 32) / 256, 256>>>();
    kern_score<<<dim3(16, 16, 8), 256>>>();
    kern_stats<<<HH * NN, 256>>>();
    kern_out  <<<dim3(16, 8), 256>>>(out);
    kern_sim  <<<NN, 256>>>(out);
}

// round 3
// speedup vs baseline: 2.8613x; 1.1063x over previous
#include <cuda_runtime.h>
#include <cuda_bf16.h>
#include <cstdint>
#include <math.h>

#define NN 2048
#define CC 1024
#define HH 8
#define DD 128

using bf16 = __nv_bfloat16;

// Scratch (device globals — no allocations anywhere)
__device__ float g_v   [(size_t)HH * NN * DD];   // fp32 v           8 MB
__device__ bf16  g_vhat[(size_t)HH * NN * DD];   // normalized bf16  4 MB
__device__ bf16  g_vb  [(size_t)HH * NN * DD];   // v bf16           4 MB
__device__ bf16  g_raw [(size_t)HH * NN * NN];   // v̂v̂ᵀ bf16        64 MB
__device__ float g_Z   [HH * NN];                // softmax row sums (m = 25 const)

// ---------------------------------------------------------------------------
// helpers
// ---------------------------------------------------------------------------
__device__ __forceinline__ uint32_t sptr(const void* p) {
    return (uint32_t)__cvta_generic_to_shared(p);
}
__device__ __forceinline__ void ldmx4(uint32_t a, uint32_t& r0, uint32_t& r1,
                                      uint32_t& r2, uint32_t& r3) {
    asm volatile("ldmatrix.sync.aligned.m8n8.x4.shared.b16 {%0,%1,%2,%3}, [%4];"
                 : "=r"(r0), "=r"(r1), "=r"(r2), "=r"(r3) : "r"(a));
}
__device__ __forceinline__ void ldmx4t(uint32_t a, uint32_t& r0, uint32_t& r1,
                                       uint32_t& r2, uint32_t& r3) {
    asm volatile("ldmatrix.sync.aligned.m8n8.x4.trans.shared.b16 {%0,%1,%2,%3}, [%4];"
                 : "=r"(r0), "=r"(r1), "=r"(r2), "=r"(r3) : "r"(a));
}
__device__ __forceinline__ void mma_bf(float* c, const uint32_t* a,
                                       uint32_t b0, uint32_t b1) {
    asm volatile("mma.sync.aligned.m16n8k16.row.col.f32.bf16.bf16.f32 "
                 "{%0,%1,%2,%3}, {%4,%5,%6,%7}, {%8,%9}, {%0,%1,%2,%3};"
                 : "+f"(c[0]), "+f"(c[1]), "+f"(c[2]), "+f"(c[3])
                 : "r"(a[0]), "r"(a[1]), "r"(a[2]), "r"(a[3]), "r"(b0), "r"(b1));
}
__device__ __forceinline__ uint32_t packbf(float x, float y) {
    __nv_bfloat162 h = __floats2bfloat162_rn(x, y);
    return *reinterpret_cast<uint32_t*>(&h);
}
__device__ __forceinline__ float2 unpackbf(uint32_t u) {
    __nv_bfloat162 h = *reinterpret_cast<__nv_bfloat162*>(&u);
    return __bfloat1622float2(h);
}
__device__ __forceinline__ void split2(float x, float y, uint32_t& hi, uint32_t& lo) {
    bf16 hx = __float2bfloat16_rn(x), hy = __float2bfloat16_rn(y);
    bf16 lx = __float2bfloat16_rn(x - __bfloat162float(hx));
    bf16 ly = __float2bfloat16_rn(y - __bfloat162float(hy));
    __nv_bfloat162 H = __halves2bfloat162(hx, hy);
    __nv_bfloat162 L = __halves2bfloat162(lx, ly);
    hi = *reinterpret_cast<uint32_t*>(&H);
    lo = *reinterpret_cast<uint32_t*>(&L);
}
__device__ __forceinline__ float block_reduce_sum(float v, float* sh) {
    #pragma unroll
    for (int o = 16; o; o >>= 1) v += __shfl_xor_sync(0xffffffffu, v, o);
    int w = threadIdx.x >> 5, l = threadIdx.x & 31;
    if (l == 0) sh[w] = v;
    __syncthreads();
    float r = sh[0];
    #pragma unroll
    for (int i = 1; i < 8; i++) r += sh[i];
    __syncthreads();
    return r;
}

// ---------------------------------------------------------------------------
// Kernel 1: v = X @ Wv^T (split-bf16, 3 MMA passes) + fused L2 normalize.
// Each block covers 128 rows × one full head (128 dims) -> per-row sumsq is
// block-local. Also writes x_ori half of the output and zeroes g_Z.
// ---------------------------------------------------------------------------
__global__ __launch_bounds__(256)
void kern_qkv(const float* __restrict__ X, const float* __restrict__ Wv,
              float* __restrict__ out) {
    __shared__ __align__(16) bf16 Ah[128][40], Al[128][40], Bh[128][40], Bl[128][40];
    __shared__ float rsum[128];
    uint32_t* AhU = (uint32_t*)&Ah[0][0]; uint32_t* AlU = (uint32_t*)&Al[0][0];
    uint32_t* BhU = (uint32_t*)&Bh[0][0]; uint32_t* BlU = (uint32_t*)&Bl[0][0];

    const int m0 = blockIdx.y * 128, n0 = blockIdx.x * 128;
    const int tid = threadIdx.x, lane = tid & 31, wid = tid >> 5;
    const int wm = wid & 3, wn = wid >> 2;
    const int fr = lane & 15, fc = (lane >> 4) * 8;
    const int lr = tid >> 1, lh = tid & 1;

    if (tid < 128) rsum[tid] = 0.0f;
    if (blockIdx.x == 0 && blockIdx.y == 0) {
        #pragma unroll
        for (int i = 0; i < 64; i++) g_Z[tid * 64 + i] = 0.0f;
    }

    float acc[2][8][4] = {};

    for (int k0 = 0; k0 < CC; k0 += 32) {
        #pragma unroll
        for (int i = 0; i < 4; i++) {
            const int c = lh * 16 + i * 4;
            float4 a = *(const float4*)&X [(size_t)(m0 + lr) * CC + k0 + c];
            float4 b = *(const float4*)&Wv[(size_t)(n0 + lr) * CC + k0 + c];
            uint32_t h0, l0, h1, l1;
            split2(a.x, a.y, h0, l0); split2(a.z, a.w, h1, l1);
            AhU[lr * 20 + c / 2] = h0; AhU[lr * 20 + c / 2 + 1] = h1;
            AlU[lr * 20 + c / 2] = l0; AlU[lr * 20 + c / 2 + 1] = l1;
            split2(b.x, b.y, h0, l0); split2(b.z, b.w, h1, l1);
            BhU[lr * 20 + c / 2] = h0; BhU[lr * 20 + c / 2 + 1] = h1;
            BlU[lr * 20 + c / 2] = l0; BlU[lr * 20 + c / 2 + 1] = l1;
        }
        __syncthreads();
        #pragma unroll
        for (int ks = 0; ks < 32; ks += 16) {
            uint32_t ah[2][4], al[2][4], bh[4][4], bl[4][4];
            #pragma unroll
            for (int i = 0; i < 2; i++) {
                ldmx4(sptr(&Ah[wm * 32 + i * 16 + fr][ks + fc]),
                      ah[i][0], ah[i][1], ah[i][2], ah[i][3]);
                ldmx4(sptr(&Al[wm * 32 + i * 16 + fr][ks + fc]),
                      al[i][0], al[i][1], al[i][2], al[i][3]);
            }
            #pragma unroll
            for (int j = 0; j < 4; j++) {
                ldmx4(sptr(&Bh[wn * 64 + j * 16 + fr][ks + fc]),
                      bh[j][0], bh[j][1], bh[j][2], bh[j][3]);
                ldmx4(sptr(&Bl[wn * 64 + j * 16 + fr][ks + fc]),
                      bl[j][0], bl[j][1], bl[j][2], bl[j][3]);
            }
            #pragma unroll
            for (int i = 0; i < 2; i++)
                #pragma unroll
                for (int j = 0; j < 4; j++) {
                    mma_bf(acc[i][2*j],   ah[i], bh[j][0], bh[j][2]);
                    mma_bf(acc[i][2*j+1], ah[i], bh[j][1], bh[j][3]);
                    mma_bf(acc[i][2*j],   ah[i], bl[j][0], bl[j][2]);
                    mma_bf(acc[i][2*j+1], ah[i], bl[j][1], bl[j][3]);
                    mma_bf(acc[i][2*j],   al[i], bh[j][0], bh[j][2]);
                    mma_bf(acc[i][2*j+1], al[i], bh[j][1], bh[j][3]);
                }
        }
        __syncthreads();
    }

    const int g = lane >> 2, t2 = (lane & 3) * 2;

    // per-row sum of squares (quad shuffle -> smem atomics)
    #pragma unroll
    for (int i = 0; i < 2; i++)
        #pragma unroll
        for (int half = 0; half < 2; half++) {
            float s = 0.0f;
            #pragma unroll
            for (int j = 0; j < 8; j++) {
                float x = acc[i][j][half*2], y = acc[i][j][half*2+1];
                s = fmaf(x, x, s); s = fmaf(y, y, s);
            }
            s += __shfl_xor_sync(0xffffffffu, s, 1);
            s += __shfl_xor_sync(0xffffffffu, s, 2);
            if ((lane & 3) == 0)
                atomicAdd(&rsum[wm * 32 + i * 16 + g + half * 8], s);
        }
    __syncthreads();

    const int h = n0 >> 7;
    #pragma unroll
    for (int i = 0; i < 2; i++)
        #pragma unroll
        for (int half = 0; half < 2; half++) {
            const int rowl = wm * 32 + i * 16 + g + half * 8;
            const int row = m0 + rowl;
            const float inv = rsqrtf(rsum[rowl]);
            #pragma unroll
            for (int j = 0; j < 8; j++) {
                const int e = wn * 64 + j * 8 + t2;
                const float x = acc[i][j][half*2], y = acc[i][j][half*2+1];
                *(float2*)&g_v[((size_t)h * NN + row) * DD + e] = make_float2(x, y);
                *(float2*)&out[(size_t)row * (2*CC) + CC + n0 + e] = make_float2(x, y);
                *(uint32_t*)&g_vb  [((size_t)h * NN + row) * DD + e] = packbf(x, y);
                *(uint32_t*)&g_vhat[((size_t)h * NN + row) * DD + e] = packbf(x*inv, y*inv);
            }
        }
}

// ---------------------------------------------------------------------------
// Kernel 2: raw[h] = v̂ v̂ᵀ — TRIANGULAR grid (136 tiles/head), mirror written
// via smem transpose. Epilogue accumulates softmax row sums into g_Z
// (exp(25*(v-1)), max known = diag = 1) from the bf16-ROUNDED values.
// ---------------------------------------------------------------------------
__global__ __launch_bounds__(256)
void kern_score() {
    __shared__ __align__(16) bf16 AB[2][128][72];   // reused as Ts after mainloop
    bf16 (*As)[72] = AB[0];
    bf16 (*Bs)[72] = AB[1];
    uint32_t* Ts = (uint32_t*)&AB[0][0][0];         // [128][65] packed bf16 pairs

    const int h = blockIdx.z;
    const int idx = blockIdx.x;
    int bj = (int)((sqrtf(8.0f * idx + 1.0f) - 1.0f) * 0.5f);
    while ((bj + 1) * (bj + 2) / 2 <= idx) bj++;
    while (bj * (bj + 1) / 2 > idx) bj--;
    const int bi = idx - bj * (bj + 1) / 2;         // 0 <= bi <= bj <= 15
    const int m0 = bi * 128, n0 = bj * 128;

    const bf16* __restrict__ V = g_vhat + (size_t)h * NN * DD;
    bf16* __restrict__ C = g_raw + (size_t)h * NN * NN;
    const int tid = threadIdx.x, lane = tid & 31, wid = tid >> 5;
    const int wm = wid & 3, wn = wid >> 2;
    const int fr = lane & 15, fc = (lane >> 4) * 8;
    const int lr = tid >> 1, lh = tid & 1;

    float acc[2][8][4] = {};

    for (int k0 = 0; k0 < DD; k0 += 64) {
        #pragma unroll
        for (int i = 0; i < 4; i++) {
            const int c = lh * 32 + i * 8;
            *(uint4*)&As[lr][c] = *(const uint4*)&V[(size_t)(m0 + lr) * DD + k0 + c];
            *(uint4*)&Bs[lr][c] = *(const uint4*)&V[(size_t)(n0 + lr) * DD + k0 + c];
        }
        __syncthreads();
        #pragma unroll
        for (int ks = 0; ks < 64; ks += 16) {
            uint32_t a_[2][4], b_[4][4];
            #pragma unroll
            for (int i = 0; i < 2; i++)
                ldmx4(sptr(&As[wm * 32 + i * 16 + fr][ks + fc]),
                      a_[i][0], a_[i][1], a_[i][2], a_[i][3]);
            #pragma unroll
            for (int j = 0; j < 4; j++)
                ldmx4(sptr(&Bs[wn * 64 + j * 16 + fr][ks + fc]),
                      b_[j][0], b_[j][1], b_[j][2], b_[j][3]);
            #pragma unroll
            for (int i = 0; i < 2; i++)
                #pragma unroll
                for (int j = 0; j < 4; j++) {
                    mma_bf(acc[i][2*j],   a_[i], b_[j][0], b_[j][2]);
                    mma_bf(acc[i][2*j+1], a_[i], b_[j][1], b_[j][3]);
                }
        }
        __syncthreads();
    }

    // direct tile write + stage bf16-rounded tile into Ts (smem reuse is safe:
    // mainloop ended with __syncthreads and As/Bs are dead)
    const int g = lane >> 2, t2 = (lane & 3) * 2;
    #pragma unroll
    for (int i = 0; i < 2; i++)
        #pragma unroll
        for (int half = 0; half < 2; half++) {
            const int r = wm * 32 + i * 16 + g + half * 8;
            #pragma unroll
            for (int j = 0; j < 8; j++) {
                const int cl = wn * 64 + j * 8 + t2;
                const uint32_t pk = packbf(acc[i][j][half*2], acc[i][j][half*2+1]);
                *(uint32_t*)&C[(size_t)(m0 + r) * NN + n0 + cl] = pk;
                Ts[r * 65 + (cl >> 1)] = pk;
            }
        }
    __syncthreads();

    // row sums -> Z[m0 + r]
    {
        const int r = tid >> 1, seg = tid & 1;
        float s = 0.0f;
        #pragma unroll 8
        for (int k = 0; k < 32; k++) {
            float2 f = unpackbf(Ts[r * 65 + seg * 32 + k]);
            s += __expf(25.0f * (f.x - 1.0f)) + __expf(25.0f * (f.y - 1.0f));
        }
        atomicAdd(&g_Z[h * NN + m0 + r], s);
    }

    if (bi != bj) {
        // column sums -> Z[n0 + c]  (mirror rows)
        {
            const int c = tid >> 1, seg = tid & 1;
            float s = 0.0f;
            #pragma unroll 8
            for (int k = 0; k < 64; k++) {
                float2 f = unpackbf(Ts[(seg * 64 + k) * 65 + (c >> 1)]);
                s += __expf(25.0f * (((c & 1) ? f.y : f.x) - 1.0f));
            }
            atomicAdd(&g_Z[h * NN + n0 + c], s);
        }
        // mirror tile write C[n0+c][m0 + ...] (coalesced via smem transpose)
        #pragma unroll 4
        for (int s2 = 0; s2 < 16; s2++) {
            const int cc = wid * 16 + s2;
            const int sel = (cc & 1) ? 0x7632 : 0x5410;
            uint32_t* o = (uint32_t*)&C[(size_t)(n0 + cc) * NN + m0];
            uint32_t A0 = Ts[(2 * lane) * 65 + (cc >> 1)];
            uint32_t B0 = Ts[(2 * lane + 1) * 65 + (cc >> 1)];
            o[lane] = __byte_perm(A0, B0, sel);
            uint32_t A1 = Ts[(2 * lane + 64) * 65 + (cc >> 1)];
            uint32_t B1 = Ts[(2 * lane + 65) * 65 + (cc >> 1)];
            o[lane + 32] = __byte_perm(A1, B1, sel);
        }
    }
}

// ---------------------------------------------------------------------------
// Kernel 3: x[h] = P_offdiag @ v (p regenerated on the fly: exp(25(raw-1))/Z)
//           + exact fp32 diagonal term in the epilogue.
// ---------------------------------------------------------------------------
__global__ __launch_bounds__(256)
void kern_out(float* __restrict__ out) {
    __shared__ __align__(16) bf16 Ap[128][40];
    __shared__ __align__(16) bf16 Vs[32][136];
    const int h = blockIdx.y, m0 = blockIdx.x * 128;
    const bf16* __restrict__ R  = g_raw + (size_t)h * NN * NN;
    const bf16* __restrict__ Vb = g_vb  + (size_t)h * NN * DD;
    const int tid = threadIdx.x, lane = tid & 31, wid = tid >> 5;
    const int wm = wid & 3, wn = wid >> 2;
    const int fr = lane & 15, fc = (lane >> 4) * 8;
    const int lr = tid >> 1, lh = tid & 1;
    const int vk = tid >> 3, vc = (tid & 7) * 16;

    const float iz = 1.0f / g_Z[h * NN + m0 + lr];

    float acc[2][8][4] = {};

    for (int k0 = 0; k0 < NN; k0 += 32) {
        #pragma unroll
        for (int i = 0; i < 2; i++) {
            const int c = lh * 16 + i * 8;
            uint4 u = *(const uint4*)&R[(size_t)(m0 + lr) * NN + k0 + c];
            const uint32_t* uu = (const uint32_t*)&u;
            uint32_t o[4];
            #pragma unroll
            for (int e = 0; e < 4; e++) {
                float2 f = unpackbf(uu[e]);
                float p0 = __expf(25.0f * (f.x - 1.0f)) * iz;
                float p1 = __expf(25.0f * (f.y - 1.0f)) * iz;
                if (k0 + c + 2*e     == m0 + lr) p0 = 0.0f;
                if (k0 + c + 2*e + 1 == m0 + lr) p1 = 0.0f;
                o[e] = packbf(p0, p1);
            }
            uint4 w; w.x = o[0]; w.y = o[1]; w.z = o[2]; w.w = o[3];
            *(uint4*)&Ap[lr][c] = w;
        }
        #pragma unroll
        for (int i = 0; i < 2; i++)
            *(uint4*)&Vs[vk][vc + i * 8] =
                *(const uint4*)&Vb[(size_t)(k0 + vk) * DD + vc + i * 8];
        __syncthreads();
        #pragma unroll
        for (int ks = 0; ks < 32; ks += 16) {
            uint32_t a_[2][4], b_[4][4];
            #pragma unroll
            for (int i = 0; i < 2; i++)
                ldmx4(sptr(&Ap[wm * 32 + i * 16 + fr][ks + fc]),
                      a_[i][0], a_[i][1], a_[i][2], a_[i][3]);
            #pragma unroll
            for (int j = 0; j < 4; j++)
                ldmx4t(sptr(&Vs[ks + fr][wn * 64 + j * 16 + fc]),
                       b_[j][0], b_[j][1], b_[j][2], b_[j][3]);
            #pragma unroll
            for (int i = 0; i < 2; i++)
                #pragma unroll
                for (int j = 0; j < 4; j++) {
                    mma_bf(acc[i][2*j],   a_[i], b_[j][0], b_[j][1]);
                    mma_bf(acc[i][2*j+1], a_[i], b_[j][2], b_[j][3]);
                }
        }
        __syncthreads();
    }

    const int g = lane >> 2, t2 = (lane & 3) * 2;
    #pragma unroll
    for (int i = 0; i < 2; i++)
        #pragma unroll
        for (int half = 0; half < 2; half++) {
            const int row = m0 + wm * 32 + i * 16 + g + half * 8;
            const float rawnn = __bfloat162float(R[(size_t)row * NN + row]);
            const float pd = __expf(25.0f * (rawnn - 1.0f)) / g_Z[h * NN + row];
            #pragma unroll
            for (int j = 0; j < 8; j++) {
                const int e = wn * 64 + j * 8 + t2;
                float2 vv = *(const float2*)&g_v[((size_t)h * NN + row) * DD + e];
                float2 o = make_float2(acc[i][j][half*2]   + pd * vv.x,
                                       acc[i][j][half*2+1] + pd * vv.y);
                *(float2*)&out[(size_t)row * (2*CC) + h * DD + e] = o;
            }
        }
}

// ---------------------------------------------------------------------------
// Kernel 4: sim_round2. attn regenerated from raw + Z; masked renorm.
// max of sa is provably <= 1 -> use constant shift (no max reduce needed).
// ---------------------------------------------------------------------------
__global__ __launch_bounds__(256)
void kern_sim(float* __restrict__ out) {
    __shared__ float sh[8];
    const int n = blockIdx.x, t = threadIdx.x;
    float sa[8] = {}, ar[8] = {};
    #pragma unroll
    for (int h = 0; h < HH; h++) {
        const size_t off = ((size_t)h * NN + n) * NN + t * 8;
        uint4 u = *(const uint4*)&g_raw[off];
        const uint32_t* uu = (const uint32_t*)&u;
        const float iz = 1.0f / g_Z[h * NN + n];
        #pragma unroll
        for (int e = 0; e < 4; e++) {
            float2 f = unpackbf(uu[e]);
            ar[2*e]   += f.x;
            ar[2*e+1] += f.y;
            sa[2*e]   += __expf(25.0f * (f.x - 1.0f)) * iz;
            sa[2*e+1] += __expf(25.0f * (f.y - 1.0f)) * iz;
        }
    }
    float e[8]; float ms = 0.0f;
    #pragma unroll
    for (int i = 0; i < 8; i++) {
        float ev = __expf(sa[i] * 0.125f - 1.0f);        // shift by known bound 1
        ev = (ar[i] > 6.0f) ? ev : 0.0f;                 // mean>0.75 <=> sum>6
        e[i] = ev; ms += ev;
    }
    ms = block_reduce_sum(ms, sh);
    const float inv = 1.0f / ms;
    const size_t base = (size_t)NN * (2*CC) + (size_t)n * NN + t * 8;
    *(float4*)&out[base]     = make_float4(e[0]*inv, e[1]*inv, e[2]*inv, e[3]*inv);
    *(float4*)&out[base + 4] = make_float4(e[4]*inv, e[5]*inv, e[6]*inv, e[7]*inv);
}

// ---------------------------------------------------------------------------
extern "C" void kernel_launch(void* const* d_in, const int* in_sizes, int n_in,
                              void* d_out, int out_size) {
    const float* x_cls = (const float*)d_in[0];
    const float* W_cls = (const float*)d_in[4];
    float* out = (float*)d_out;
    const float* Wv = W_cls + (size_t)2 * CC * CC;

    kern_qkv  <<<dim3(8, 16), 256>>>(x_cls, Wv, out);
    kern_score<<<dim3(136, 1, 8), 256>>>();
    kern_out  <<<dim3(16, 8), 256>>>(out);
    kern_sim  <<<NN, 256>>>(out);
}